// round 1
// baseline (speedup 1.0000x reference)
#include <cuda_runtime.h>
#include <math.h>

#define BB   2
#define NN   512
#define CC   256
#define OUTD 256
#define HH   4
#define HD   64
#define ROWS (BB*NN)   // 1024

// ---- scratch (device globals; no allocation allowed) ----
__device__ float g_hi[ROWS*OUTD];
__device__ float g_hj[ROWS*OUTD];
__device__ float g_v [ROWS*OUTD];
__device__ float g_s1i[ROWS];
__device__ float g_s2i[ROWS];
__device__ float g_s1j[ROWS];
__device__ float g_s2j[ROWS];
__device__ float g_logits[ROWS*NN*HH];   // 8 MB, softmaxed in place
__device__ float g_mid[ROWS*OUTD];

// ============================================================
// K1: h_i = x@We[:C]+be ; h_j = x@We[C:] ; v = x@Wv+bv
//     + per-row sum / sumsq for h_i, h_j
// grid (64, 3), block 256
// ============================================================
__global__ __launch_bounds__(256) void k1_proj(
    const float* __restrict__ x, const float* __restrict__ We,
    const float* __restrict__ be, const float* __restrict__ Wv,
    const float* __restrict__ bv)
{
    __shared__ float sx[16][257];
    int row0 = blockIdx.x * 16;
    int mat  = blockIdx.y;

    for (int t = threadIdx.x; t < 16*256; t += 256)
        sx[t >> 8][t & 255] = x[row0*256 + t];
    __syncthreads();

    int col = threadIdx.x;
    const float* W; float bias; float* out;
    if (mat == 0)      { W = We;           bias = be[col]; out = g_hi; }
    else if (mat == 1) { W = We + 256*256; bias = 0.f;     out = g_hj; }
    else               { W = Wv;           bias = bv[col]; out = g_v;  }

    float acc[16];
    #pragma unroll
    for (int r = 0; r < 16; r++) acc[r] = bias;

    for (int k = 0; k < 256; k++) {
        float w = W[k*256 + col];
        #pragma unroll
        for (int r = 0; r < 16; r++) acc[r] = fmaf(sx[r][k], w, acc[r]);
    }
    #pragma unroll
    for (int r = 0; r < 16; r++) out[(row0 + r)*256 + col] = acc[r];

    if (mat < 2) {
        __syncthreads();
        #pragma unroll
        for (int r = 0; r < 16; r++) sx[r][col] = acc[r];
        __syncthreads();
        int wid = threadIdx.x >> 5, lane = threadIdx.x & 31;
        float* s1 = (mat == 0) ? g_s1i : g_s1j;
        float* s2 = (mat == 0) ? g_s2i : g_s2j;
        for (int r = wid; r < 16; r += 8) {
            float a = 0.f, q = 0.f;
            for (int c = lane; c < 256; c += 32) {
                float v = sx[r][c]; a += v; q = fmaf(v, v, q);
            }
            #pragma unroll
            for (int off = 16; off; off >>= 1) {
                a += __shfl_xor_sync(0xffffffffu, a, off);
                q += __shfl_xor_sync(0xffffffffu, q, off);
            }
            if (lane == 0) { s1[row0 + r] = a; s2[row0 + r] = q; }
        }
    }
}

// ============================================================
// K2: the dominant pairwise kernel.
//   For every (b,i,j): LN(h_i+h_j) -> gelu -> @W2 + b2 -> logits
//   LN stats via factored sums + per-pair dot product.
// grid (128, 4) : blockIdx.x = i-tile (8 rows), blockIdx.y = 128-wide j chunk
// block 256 : warp = 1 i-row x 32 j-rows
// ============================================================
#define TI 8
#define TJ 32

__global__ __launch_bounds__(256) void k2_pair(
    const float* __restrict__ ln1g, const float* __restrict__ ln1b,
    const float* __restrict__ W2,   const float* __restrict__ b2)
{
    __shared__ float shi[TI][257];
    __shared__ float shj[TJ][257];
    __shared__ float sg[256], sb[256];
    __shared__ float sW2[256*4];
    __shared__ float s1i[TI], s2i[TI], s1j[TJ], s2j[TJ];
    __shared__ float sb2[4];

    int ri0 = blockIdx.x * TI;        // global row in [0,1024)
    int b   = ri0 / NN;
    int tid = threadIdx.x;

    for (int t = tid; t < TI*256; t += 256)
        shi[t >> 8][t & 255] = g_hi[ri0*256 + t];
    sg[tid] = ln1g[tid];
    sb[tid] = ln1b[tid];
    ((float4*)sW2)[tid] = ((const float4*)W2)[tid];   // 1024 floats
    if (tid < TI) { s1i[tid] = g_s1i[ri0 + tid]; s2i[tid] = g_s2i[ri0 + tid]; }
    if (tid < 4)  sb2[tid] = b2[tid];

    int ti = tid >> 5;       // constant within a warp -> broadcast reads of shi
    int tj = tid & 31;       // lane -> conflict-free reads of shj (pad 257)

    for (int jt = 0; jt < 4; jt++) {
        int j0  = blockIdx.y * 128 + jt * 32;   // j within batch
        int rj0 = b * NN + j0;
        __syncthreads();
        for (int t = tid; t < TJ*256; t += 256)
            shj[t >> 8][t & 255] = g_hj[rj0*256 + t];
        if (tid < TJ) { s1j[tid] = g_s1j[rj0 + tid]; s2j[tid] = g_s2j[rj0 + tid]; }
        __syncthreads();

        // pass A: dot(h_i, h_j) for the cross term of Var
        float dot = 0.f;
        #pragma unroll 8
        for (int c = 0; c < 256; c++)
            dot = fmaf(shi[ti][c], shj[tj][c], dot);

        float mu   = (s1i[ti] + s1j[tj]) * (1.f/256.f);
        float ex2  = (s2i[ti] + s2j[tj] + 2.f*dot) * (1.f/256.f);
        float var  = ex2 - mu*mu;
        float rstd = rsqrtf(var + 1e-5f);
        float nmr  = -mu * rstd;

        float a0 = sb2[0], a1 = sb2[1], a2 = sb2[2], a3 = sb2[3];
        #pragma unroll 4
        for (int c = 0; c < 256; c++) {
            float e  = shi[ti][c] + shj[tj][c];
            float z  = fmaf(e, rstd, nmr);
            float y  = fmaf(z, sg[c], sb[c]);
            float gl = 0.5f * y * (1.f + erff(y * 0.70710678118654752f));
            float4 w4 = ((const float4*)sW2)[c];
            a0 = fmaf(gl, w4.x, a0);
            a1 = fmaf(gl, w4.y, a1);
            a2 = fmaf(gl, w4.z, a2);
            a3 = fmaf(gl, w4.w, a3);
        }
        ((float4*)g_logits)[(ri0 + ti)*NN + (j0 + tj)] =
            make_float4(a0, a1, a2, a3);
    }
}

// ============================================================
// K3: softmax over j for each (b,i,h). warp per row.
// grid 512, block 256 (8 warps)
// ============================================================
__global__ __launch_bounds__(256) void k3_softmax()
{
    int row  = blockIdx.x * 8 + (threadIdx.x >> 5);  // 0..4095
    int lane = threadIdx.x & 31;
    int ri = row >> 2, h = row & 3;
    float* p = g_logits + (size_t)ri*NN*4 + h;

    float vals[16];
    float m = -1e30f;
    #pragma unroll
    for (int k = 0; k < 16; k++) {
        vals[k] = p[(lane + 32*k)*4];
        m = fmaxf(m, vals[k]);
    }
    #pragma unroll
    for (int off = 16; off; off >>= 1)
        m = fmaxf(m, __shfl_xor_sync(0xffffffffu, m, off));
    float s = 0.f;
    #pragma unroll
    for (int k = 0; k < 16; k++) { vals[k] = __expf(vals[k] - m); s += vals[k]; }
    #pragma unroll
    for (int off = 16; off; off >>= 1)
        s += __shfl_xor_sync(0xffffffffu, s, off);
    float inv = 1.f / s;
    #pragma unroll
    for (int k = 0; k < 16; k++) p[(lane + 32*k)*4] = vals[k] * inv;
}

// ============================================================
// K4: out_mid[b,i,h,d] = sum_j adj[b,i,j,h] * v[b,j,h,d]
// 8 GEMMs [512x512]x[512x64]; block tile 64i x 64d, thread 4x4
// grid (8, 8) = (i-tile, b*H+h), block 256
// ============================================================
__global__ __launch_bounds__(256) void k4_av()
{
    int bh = blockIdx.y; int b = bh >> 2, h = bh & 3;
    int i0 = blockIdx.x * 64;
    __shared__ float sa[64][65];
    __shared__ float sv[64][65];
    int tid = threadIdx.x;
    int tx = tid & 15, ty = tid >> 4;

    float acc[4][4] = {};
    for (int j0 = 0; j0 < NN; j0 += 64) {
        __syncthreads();
        for (int t = tid; t < 4096; t += 256) {
            int r = t >> 6, c = t & 63;
            sa[r][c] = g_logits[((size_t)(b*NN + i0 + r)*NN + j0 + c)*4 + h];
            sv[r][c] = g_v[(b*NN + j0 + r)*256 + h*64 + c];
        }
        __syncthreads();
        #pragma unroll 8
        for (int j = 0; j < 64; j++) {
            float av[4], vv[4];
            #pragma unroll
            for (int u = 0; u < 4; u++) { av[u] = sa[ty*4+u][j]; vv[u] = sv[j][tx*4+u]; }
            #pragma unroll
            for (int u = 0; u < 4; u++)
                #pragma unroll
                for (int w = 0; w < 4; w++)
                    acc[u][w] = fmaf(av[u], vv[w], acc[u][w]);
        }
    }
    #pragma unroll
    for (int u = 0; u < 4; u++)
        #pragma unroll
        for (int w = 0; w < 4; w++)
            g_mid[(b*NN + i0 + ty*4 + u)*256 + h*64 + tx*4 + w] = acc[u][w];
}

// ============================================================
// K5: out = LN2( mid@Wo + bo + x )
// grid 128 (8 rows each), block 256
// ============================================================
__global__ __launch_bounds__(256) void k5_out(
    const float* __restrict__ x,  const float* __restrict__ Wo,
    const float* __restrict__ bo, const float* __restrict__ g2,
    const float* __restrict__ bt, float* __restrict__ out)
{
    __shared__ float sm[8][257];
    __shared__ float smu[8], srs[8];
    int row0 = blockIdx.x * 8;
    int tid  = threadIdx.x;

    for (int t = tid; t < 8*256; t += 256)
        sm[t >> 8][t & 255] = g_mid[row0*256 + t];
    __syncthreads();

    int col = tid;
    float acc[8];
    #pragma unroll
    for (int r = 0; r < 8; r++) acc[r] = bo[col];
    for (int k = 0; k < 256; k++) {
        float w = Wo[k*256 + col];
        #pragma unroll
        for (int r = 0; r < 8; r++) acc[r] = fmaf(sm[r][k], w, acc[r]);
    }
    #pragma unroll
    for (int r = 0; r < 8; r++) acc[r] += x[(row0 + r)*256 + col];
    __syncthreads();
    #pragma unroll
    for (int r = 0; r < 8; r++) sm[r][col] = acc[r];
    __syncthreads();

    int wid = tid >> 5, lane = tid & 31;
    {
        float a = 0.f, q = 0.f;
        for (int c = lane; c < 256; c += 32) {
            float v = sm[wid][c]; a += v; q = fmaf(v, v, q);
        }
        #pragma unroll
        for (int off = 16; off; off >>= 1) {
            a += __shfl_xor_sync(0xffffffffu, a, off);
            q += __shfl_xor_sync(0xffffffffu, q, off);
        }
        if (lane == 0) {
            float mu = a * (1.f/256.f);
            float var = q * (1.f/256.f) - mu*mu;
            smu[wid] = mu; srs[wid] = rsqrtf(var + 1e-5f);
        }
    }
    __syncthreads();
    float g = g2[col], bb = bt[col];
    #pragma unroll
    for (int r = 0; r < 8; r++)
        out[(row0 + r)*256 + col] = (sm[r][col] - smu[r]) * srs[r] * g + bb;
}

// ============================================================
extern "C" void kernel_launch(void* const* d_in, const int* in_sizes, int n_in,
                              void* d_out, int out_size)
{
    const float* x    = (const float*)d_in[0];
    const float* We   = (const float*)d_in[1];
    const float* be   = (const float*)d_in[2];
    const float* ln1g = (const float*)d_in[3];
    const float* ln1b = (const float*)d_in[4];
    const float* W2   = (const float*)d_in[5];
    const float* b2   = (const float*)d_in[6];
    const float* Wv   = (const float*)d_in[7];
    const float* bv   = (const float*)d_in[8];
    const float* Wo   = (const float*)d_in[9];
    const float* bo   = (const float*)d_in[10];
    const float* ln2g = (const float*)d_in[11];
    const float* ln2b = (const float*)d_in[12];
    float* out = (float*)d_out;

    k1_proj   <<<dim3(64, 3),  256>>>(x, We, be, Wv, bv);
    k2_pair   <<<dim3(128, 4), 256>>>(ln1g, ln1b, W2, b2);
    k3_softmax<<<512,          256>>>();
    k4_av     <<<dim3(8, 8),   256>>>();
    k5_out    <<<128,          256>>>(x, Wo, bo, ln2g, ln2b, out);
}

// round 2
// speedup vs baseline: 1.2676x; 1.2676x over previous
#include <cuda_runtime.h>
#include <math.h>

#define BB   2
#define NN   512
#define CC   256
#define OUTD 256
#define HH   4
#define HD   64
#define ROWS (BB*NN)   // 1024

// ---- scratch (device globals; no allocation allowed) ----
__device__ float g_hi[ROWS*OUTD];
__device__ float g_hj[ROWS*OUTD];
__device__ float g_v [ROWS*OUTD];
__device__ float g_s1i[ROWS];
__device__ float g_s2i[ROWS];
__device__ float g_s1j[ROWS];
__device__ float g_s2j[ROWS];
__device__ float g_logits[ROWS*NN*HH];          // [ri][j][h], 8 MB
__device__ float g_adjT[BB*HH*NN*NN];           // [b*4+h][i][j], 8 MB
__device__ float g_mid[ROWS*OUTD];

// ---------------- packed f32x2 helpers (Blackwell) ----------------
typedef unsigned long long u64;

__device__ __forceinline__ u64 pk2(float lo, float hi) {
    u64 r; asm("mov.b64 %0,{%1,%2};" : "=l"(r) : "f"(lo), "f"(hi)); return r;
}
__device__ __forceinline__ u64 splat(float x) {
    u64 r; asm("mov.b64 %0,{%1,%1};" : "=l"(r) : "f"(x)); return r;
}
__device__ __forceinline__ void upk(u64 a, float& x, float& y) {
    asm("mov.b64 {%0,%1},%2;" : "=f"(x), "=f"(y) : "l"(a));
}
__device__ __forceinline__ u64 f2add(u64 a, u64 b) {
    u64 d; asm("add.rn.f32x2 %0,%1,%2;" : "=l"(d) : "l"(a), "l"(b)); return d;
}
__device__ __forceinline__ u64 f2mul(u64 a, u64 b) {
    u64 d; asm("mul.rn.f32x2 %0,%1,%2;" : "=l"(d) : "l"(a), "l"(b)); return d;
}
__device__ __forceinline__ u64 f2fma(u64 a, u64 b, u64 c) {
    u64 d; asm("fma.rn.f32x2 %0,%1,%2,%3;" : "=l"(d) : "l"(a), "l"(b), "l"(c)); return d;
}
__device__ __forceinline__ float rcpa(float x) {
    float r; asm("rcp.approx.f32 %0,%1;" : "=f"(r) : "f"(x)); return r;
}
__device__ __forceinline__ float ex2a(float x) {
    float r; asm("ex2.approx.f32 %0,%1;" : "=f"(r) : "f"(x)); return r;
}

// ============================================================
// K1: h_i = x@We[:C]+be ; h_j = x@We[C:] ; v = x@Wv+bv
//     + per-row sum / sumsq for h_i, h_j
// grid (64, 3), block 256
// ============================================================
__global__ __launch_bounds__(256) void k1_proj(
    const float* __restrict__ x, const float* __restrict__ We,
    const float* __restrict__ be, const float* __restrict__ Wv,
    const float* __restrict__ bv)
{
    __shared__ float sx[16][257];
    int row0 = blockIdx.x * 16;
    int mat  = blockIdx.y;

    for (int t = threadIdx.x; t < 16*256; t += 256)
        sx[t >> 8][t & 255] = x[row0*256 + t];
    __syncthreads();

    int col = threadIdx.x;
    const float* W; float bias; float* out;
    if (mat == 0)      { W = We;           bias = be[col]; out = g_hi; }
    else if (mat == 1) { W = We + 256*256; bias = 0.f;     out = g_hj; }
    else               { W = Wv;           bias = bv[col]; out = g_v;  }

    float acc[16];
    #pragma unroll
    for (int r = 0; r < 16; r++) acc[r] = bias;

    for (int k = 0; k < 256; k++) {
        float w = W[k*256 + col];
        #pragma unroll
        for (int r = 0; r < 16; r++) acc[r] = fmaf(sx[r][k], w, acc[r]);
    }
    #pragma unroll
    for (int r = 0; r < 16; r++) out[(row0 + r)*256 + col] = acc[r];

    if (mat < 2) {
        __syncthreads();
        #pragma unroll
        for (int r = 0; r < 16; r++) sx[r][col] = acc[r];
        __syncthreads();
        int wid = threadIdx.x >> 5, lane = threadIdx.x & 31;
        float* s1 = (mat == 0) ? g_s1i : g_s1j;
        float* s2 = (mat == 0) ? g_s2i : g_s2j;
        for (int r = wid; r < 16; r += 8) {
            float a = 0.f, q = 0.f;
            for (int c = lane; c < 256; c += 32) {
                float v = sx[r][c]; a += v; q = fmaf(v, v, q);
            }
            #pragma unroll
            for (int off = 16; off; off >>= 1) {
                a += __shfl_xor_sync(0xffffffffu, a, off);
                q += __shfl_xor_sync(0xffffffffu, q, off);
            }
            if (lane == 0) { s1[row0 + r] = a; s2[row0 + r] = q; }
        }
    }
}

// ============================================================
// K2: dominant pairwise kernel, f32x2-packed over channel pairs.
//   LN stats factored:  mu = (s1i+s1j)/256,
//   E[e^2] = (s2i+s2j+2*dot)/256.
//   GELU exact via Abramowitz-Stegun 7.1.26 erf (abs err 1.5e-7),
//   branchless: rcp.approx + ex2.approx per channel.
// grid (128, 4), block 256; warp = 1 i-row x 32 j-rows
// ============================================================
#define TI 8
#define SJ 258   // 8B-aligned row stride, conflict-free for LDS.64

__global__ __launch_bounds__(256) void k2_pair(
    const float* __restrict__ ln1g, const float* __restrict__ ln1b,
    const float* __restrict__ W2,   const float* __restrict__ b2)
{
    __shared__ float shi[TI][SJ];
    __shared__ float shj[32][SJ];
    __shared__ float sg[256], sb[256];
    __shared__ float4 sWa[128], sWb[128];   // h01 / h23 channel-pair packs
    __shared__ float s1i[TI], s2i[TI], s1j[32], s2j[32];
    __shared__ float sb2[4];

    int ri0 = blockIdx.x * TI;
    int b   = ri0 / NN;
    int tid = threadIdx.x;

    for (int t = tid; t < TI*256; t += 256)
        shi[t >> 8][t & 255] = g_hi[ri0*256 + t];
    sg[tid] = ln1g[tid];
    sb[tid] = ln1b[tid];
    if (tid < 128) {
        const float* w = W2 + tid*8;   // channels 2t,2t+1 x 4 heads
        sWa[tid] = make_float4(w[0], w[4], w[1], w[5]);
        sWb[tid] = make_float4(w[2], w[6], w[3], w[7]);
    }
    if (tid < TI) { s1i[tid] = g_s1i[ri0 + tid]; s2i[tid] = g_s2i[ri0 + tid]; }
    if (tid < 4)  sb2[tid] = b2[tid];

    int ti = tid >> 5;
    int tj = tid & 31;

    // constants (hoisted)
    const u64 ONE  = splat(1.0f);
    const u64 M1   = splat(-1.0f);
    const u64 HALF = splat(0.5f);
    const u64 PR   = splat(0.3275911f * 0.70710678118654752f); // p/sqrt2
    const u64 NL   = splat(-0.72134752044448170f);             // -0.5*log2(e)
    const u64 A5   = splat(1.061405429f);
    const u64 A4   = splat(-1.453152027f);
    const u64 A3   = splat(1.421413741f);
    const u64 A2   = splat(-0.284496736f);
    const u64 A1   = splat(0.254829592f);
    const u64 SGNM = 0x8000000080000000ULL;
    const u64 ABSM = 0x7fffffff7fffffffULL;

    for (int jt = 0; jt < 4; jt++) {
        int j0  = blockIdx.y * 128 + jt * 32;
        int rj0 = b * NN + j0;
        __syncthreads();
        for (int t = tid; t < 32*256; t += 256)
            shj[t >> 8][t & 255] = g_hj[rj0*256 + t];
        if (tid < 32) { s1j[tid] = g_s1j[rj0 + tid]; s2j[tid] = g_s2j[rj0 + tid]; }
        __syncthreads();

        // pass A: packed dot(h_i, h_j)
        u64 dac = splat(0.f);
        #pragma unroll 8
        for (int c2 = 0; c2 < 128; c2++) {
            float2 a2v = *(const float2*)&shi[ti][2*c2];
            float2 b2v = *(const float2*)&shj[tj][2*c2];
            dac = f2fma(pk2(a2v.x, a2v.y), pk2(b2v.x, b2v.y), dac);
        }
        float dlo, dhi; upk(dac, dlo, dhi);
        float dot = dlo + dhi;

        float mu   = (s1i[ti] + s1j[tj]) * (1.f/256.f);
        float ex2  = (s2i[ti] + s2j[tj] + 2.f*dot) * (1.f/256.f);
        float var  = ex2 - mu*mu;
        float rstd = rsqrtf(var + 1e-5f);
        u64 rstd2 = splat(rstd);
        u64 nmr2  = splat(-mu * rstd);

        u64 acc0 = splat(0.f), acc1 = splat(0.f), acc2 = splat(0.f), acc3 = splat(0.f);
        #pragma unroll 4
        for (int c2 = 0; c2 < 128; c2++) {
            float2 hiv = *(const float2*)&shi[ti][2*c2];
            float2 hjv = *(const float2*)&shj[tj][2*c2];
            u64 e = f2add(pk2(hiv.x, hiv.y), pk2(hjv.x, hjv.y));
            u64 z = f2fma(e, rstd2, nmr2);
            float2 gv = *(const float2*)&sg[2*c2];
            float2 bv = *(const float2*)&sb[2*c2];
            u64 y = f2fma(z, pk2(gv.x, gv.y), pk2(bv.x, bv.y));

            // erf(y/sqrt2), A&S 7.1.26, branchless packed
            u64 ay = y & ABSM;
            u64 d  = f2fma(ay, PR, ONE);
            float dl, dh; upk(d, dl, dh);
            u64 t = pk2(rcpa(dl), rcpa(dh));
            u64 q  = f2mul(y, y);
            u64 ea = f2mul(q, NL);
            float el, eh; upk(ea, el, eh);
            u64 ex = pk2(ex2a(el), ex2a(eh));
            u64 P = f2fma(A5, t, A4);
            P = f2fma(P, t, A3);
            P = f2fma(P, t, A2);
            P = f2fma(P, t, A1);
            P = f2mul(P, t);
            u64 r   = f2mul(P, ex);
            u64 erf = f2fma(r, M1, ONE);          // 1 - r  (>= 0)
            erf ^= (y & SGNM);                    // sign transfer
            u64 u = f2mul(y, HALF);
            u64 g = f2fma(u, erf, u);             // 0.5y(1+erf)

            ulonglong2 wa = ((const ulonglong2*)sWa)[c2];
            ulonglong2 wb = ((const ulonglong2*)sWb)[c2];
            acc0 = f2fma(g, wa.x, acc0);
            acc1 = f2fma(g, wa.y, acc1);
            acc2 = f2fma(g, wb.x, acc2);
            acc3 = f2fma(g, wb.y, acc3);
        }
        float x0, x1, y0, y1, z0, z1, w0, w1;
        upk(acc0, x0, x1); upk(acc1, y0, y1);
        upk(acc2, z0, z1); upk(acc3, w0, w1);
        ((float4*)g_logits)[(ri0 + ti)*NN + (j0 + tj)] =
            make_float4(x0 + x1 + sb2[0], y0 + y1 + sb2[1],
                        z0 + z1 + sb2[2], w0 + w1 + sb2[3]);
    }
}

// ============================================================
// K3: softmax over j per (b,i,h); writes TRANSPOSED adj [b,h,i,j]
// grid 512, block 256 (8 warps; warp per (ri,h) row)
// ============================================================
__global__ __launch_bounds__(256) void k3_softmax()
{
    int row  = blockIdx.x * 8 + (threadIdx.x >> 5);  // 0..4095
    int lane = threadIdx.x & 31;
    int ri = row >> 2, h = row & 3;
    const float* p = g_logits + (size_t)ri*NN*4 + h;
    int b = ri >> 9, i = ri & 511;
    float* q = g_adjT + ((size_t)(b*4 + h)*NN + i)*NN;

    float vals[16];
    float m = -1e30f;
    #pragma unroll
    for (int k = 0; k < 16; k++) {
        vals[k] = p[(lane + 32*k)*4];
        m = fmaxf(m, vals[k]);
    }
    #pragma unroll
    for (int off = 16; off; off >>= 1)
        m = fmaxf(m, __shfl_xor_sync(0xffffffffu, m, off));
    float s = 0.f;
    #pragma unroll
    for (int k = 0; k < 16; k++) { vals[k] = __expf(vals[k] - m); s += vals[k]; }
    #pragma unroll
    for (int off = 16; off; off >>= 1)
        s += __shfl_xor_sync(0xffffffffu, s, off);
    float inv = 1.f / s;
    #pragma unroll
    for (int k = 0; k < 16; k++) q[lane + 32*k] = vals[k] * inv;
}

// ============================================================
// K4: mid[b,i,h,d] = sum_j adjT[b,h,i,j] * v[b,j,h,d]
// 32i x 64d tiles -> grid (16, 8) = 128 blocks; thread 2x4
// ============================================================
__global__ __launch_bounds__(256) void k4_av()
{
    int bh = blockIdx.y; int b = bh >> 2, h = bh & 3;
    int i0 = blockIdx.x * 32;
    __shared__ float sa[32][68];
    __shared__ float sv[64][68];
    int tid = threadIdx.x;
    int tx = tid & 15, ty = tid >> 4;
    const float* A = g_adjT + (size_t)bh * NN * NN;

    float acc[2][4] = {};
    for (int j0 = 0; j0 < NN; j0 += 64) {
        __syncthreads();
        // sa: 32x64 = 512 float4 loads
        for (int t = tid; t < 512; t += 256) {
            int r = t >> 4, c = (t & 15) * 4;
            float4 v4 = *(const float4*)&A[(i0 + r)*NN + j0 + c];
            *(float4*)&sa[r][c] = v4;
        }
        // sv: 64x64 = 1024 float4 loads
        for (int t = tid; t < 1024; t += 256) {
            int r = t >> 4, c = (t & 15) * 4;
            float4 v4 = *(const float4*)&g_v[(b*NN + j0 + r)*256 + h*64 + c];
            *(float4*)&sv[r][c] = v4;
        }
        __syncthreads();
        #pragma unroll 8
        for (int j = 0; j < 64; j++) {
            float a0 = sa[ty*2][j], a1 = sa[ty*2 + 1][j];
            float4 v4 = *(const float4*)&sv[j][tx*4];
            acc[0][0] = fmaf(a0, v4.x, acc[0][0]);
            acc[0][1] = fmaf(a0, v4.y, acc[0][1]);
            acc[0][2] = fmaf(a0, v4.z, acc[0][2]);
            acc[0][3] = fmaf(a0, v4.w, acc[0][3]);
            acc[1][0] = fmaf(a1, v4.x, acc[1][0]);
            acc[1][1] = fmaf(a1, v4.y, acc[1][1]);
            acc[1][2] = fmaf(a1, v4.z, acc[1][2]);
            acc[1][3] = fmaf(a1, v4.w, acc[1][3]);
        }
    }
    #pragma unroll
    for (int u = 0; u < 2; u++)
        #pragma unroll
        for (int w = 0; w < 4; w++)
            g_mid[(b*NN + i0 + ty*2 + u)*256 + h*64 + tx*4 + w] = acc[u][w];
}

// ============================================================
// K5: out = LN2( mid@Wo + bo + x )
// grid 128 (8 rows each), block 256
// ============================================================
__global__ __launch_bounds__(256) void k5_out(
    const float* __restrict__ x,  const float* __restrict__ Wo,
    const float* __restrict__ bo, const float* __restrict__ g2,
    const float* __restrict__ bt, float* __restrict__ out)
{
    __shared__ float sm[8][257];
    __shared__ float smu[8], srs[8];
    int row0 = blockIdx.x * 8;
    int tid  = threadIdx.x;

    for (int t = tid; t < 8*256; t += 256)
        sm[t >> 8][t & 255] = g_mid[row0*256 + t];
    __syncthreads();

    int col = tid;
    float acc[8];
    #pragma unroll
    for (int r = 0; r < 8; r++) acc[r] = bo[col];
    for (int k = 0; k < 256; k++) {
        float w = Wo[k*256 + col];
        #pragma unroll
        for (int r = 0; r < 8; r++) acc[r] = fmaf(sm[r][k], w, acc[r]);
    }
    #pragma unroll
    for (int r = 0; r < 8; r++) acc[r] += x[(row0 + r)*256 + col];
    __syncthreads();
    #pragma unroll
    for (int r = 0; r < 8; r++) sm[r][col] = acc[r];
    __syncthreads();

    int wid = tid >> 5, lane = tid & 31;
    {
        float a = 0.f, q = 0.f;
        for (int c = lane; c < 256; c += 32) {
            float v = sm[wid][c]; a += v; q = fmaf(v, v, q);
        }
        #pragma unroll
        for (int off = 16; off; off >>= 1) {
            a += __shfl_xor_sync(0xffffffffu, a, off);
            q += __shfl_xor_sync(0xffffffffu, q, off);
        }
        if (lane == 0) {
            float mu = a * (1.f/256.f);
            float var = q * (1.f/256.f) - mu*mu;
            smu[wid] = mu; srs[wid] = rsqrtf(var + 1e-5f);
        }
    }
    __syncthreads();
    float g = g2[col], bb = bt[col];
    #pragma unroll
    for (int r = 0; r < 8; r++)
        out[(row0 + r)*256 + col] = (sm[r][col] - smu[r]) * srs[r] * g + bb;
}

// ============================================================
extern "C" void kernel_launch(void* const* d_in, const int* in_sizes, int n_in,
                              void* d_out, int out_size)
{
    const float* x    = (const float*)d_in[0];
    const float* We   = (const float*)d_in[1];
    const float* be   = (const float*)d_in[2];
    const float* ln1g = (const float*)d_in[3];
    const float* ln1b = (const float*)d_in[4];
    const float* W2   = (const float*)d_in[5];
    const float* b2   = (const float*)d_in[6];
    const float* Wv   = (const float*)d_in[7];
    const float* bv   = (const float*)d_in[8];
    const float* Wo   = (const float*)d_in[9];
    const float* bo   = (const float*)d_in[10];
    const float* ln2g = (const float*)d_in[11];
    const float* ln2b = (const float*)d_in[12];
    float* out = (float*)d_out;

    k1_proj   <<<dim3(64, 3),  256>>>(x, We, be, Wv, bv);
    k2_pair   <<<dim3(128, 4), 256>>>(ln1g, ln1b, W2, b2);
    k3_softmax<<<512,          256>>>();
    k4_av     <<<dim3(16, 8),  256>>>();
    k5_out    <<<128,          256>>>(x, Wo, bo, ln2g, ln2b, out);
}